// round 13
// baseline (speedup 1.0000x reference)
#include <cuda_runtime.h>
#include <cuda_fp16.h>
#include <cstdint>

// Problem constants (fixed by the dataset)
#define BB 32      // batch
#define II 2048    // input capsules
#define CC 16      // input atoms (contraction dim)
#define DD 32      // output capsules
#define AA 16      // output atoms
#define OO 512     // DD*AA
#define BO (BB*OO) // 16384
#define NBMAX 160
#define NT 1024

typedef unsigned long long ull;

// Scratch (static __device__ arrays: no dynamic allocation)
__device__ float  g_part[(size_t)NBMAX * BO];        // per-block partials, 10.5 MB (L2)
__device__ float  g_actS[BO];                        // act0, then act0+act1
__device__ unsigned g_count;                          // barrier arrive counter (self-resetting)
__device__ volatile unsigned g_sense;                 // barrier generation (monotonic)

// ---------------- packed f32x2 helpers ----------------
__device__ __forceinline__ ull pack2(float lo, float hi) {
    ull r; asm("mov.b64 %0, {%1,%2};" : "=l"(r) : "f"(lo), "f"(hi)); return r;
}
__device__ __forceinline__ void unpack2(ull v, float& lo, float& hi) {
    asm("mov.b64 {%0,%1}, %2;" : "=f"(lo), "=f"(hi) : "l"(v));
}
__device__ __forceinline__ void fma2(ull& d, ull a, ull b) {
    asm("fma.rn.f32x2 %0, %1, %2, %0;" : "+l"(d) : "l"(a), "l"(b));
}

// ---------------- mma helpers ----------------
__device__ __forceinline__ void ldsm_x4(unsigned& r0, unsigned& r1, unsigned& r2, unsigned& r3,
                                        unsigned addr) {
    asm volatile("ldmatrix.sync.aligned.m8n8.x4.shared.b16 {%0,%1,%2,%3}, [%4];"
                 : "=r"(r0), "=r"(r1), "=r"(r2), "=r"(r3) : "r"(addr));
}
__device__ __forceinline__ void ldsm_x4_trans(unsigned& r0, unsigned& r1, unsigned& r2, unsigned& r3,
                                              unsigned addr) {
    asm volatile("ldmatrix.sync.aligned.m8n8.x4.trans.shared.b16 {%0,%1,%2,%3}, [%4];"
                 : "=r"(r0), "=r"(r1), "=r"(r2), "=r"(r3) : "r"(addr));
}
__device__ __forceinline__ void mma16816(float& d0, float& d1, float& d2, float& d3,
                                         unsigned a0, unsigned a1, unsigned a2, unsigned a3,
                                         unsigned b0, unsigned b1) {
    asm volatile(
        "mma.sync.aligned.m16n8k16.row.col.f32.f16.f16.f32 "
        "{%0,%1,%2,%3}, {%4,%5,%6,%7}, {%8,%9}, {%10,%11,%12,%13};"
        : "=f"(d0), "=f"(d1), "=f"(d2), "=f"(d3)
        : "r"(a0), "r"(a1), "r"(a2), "r"(a3), "r"(b0), "r"(b1),
          "f"(0.f), "f"(0.f), "f"(0.f), "f"(0.f));
}
__device__ __forceinline__ unsigned cvt_h2(float hi, float lo) {
    unsigned v; asm("cvt.rn.f16x2.f32 %0, %1, %2;" : "=r"(v) : "f"(hi), "f"(lo)); return v;
}

// smem layout: W fp16 [2][16384] @0; x fp16 [2][1536] @32768; vote stage @35840
#define WBUF_BYTES 16384
#define XBUF_OFF   32768
#define XBUF_BYTES 1536              // 32 rows x 48 B (32 B data + 16 B pad)
#define VSTAGE_OFF 35840
#define VROW_B     1040              // 1024 B data + 16 B pad
#define SMEM_TOTAL (VSTAGE_OFF + BB * VROW_B + 64)

// ---------------------------------------------------------------------------
// Software grid barrier (sense-reversing). nb blocks co-resident (1/SM).
// ---------------------------------------------------------------------------
__device__ __forceinline__ void grid_sync(int nb) {
    __syncthreads();
    if (threadIdx.x == 0) {
        unsigned gen = g_sense;
        __threadfence();
        if (atomicAdd(&g_count, 1u) == (unsigned)(nb - 1)) {
            g_count = 0;
            __threadfence();
            g_sense = gen + 1;
        } else {
            while (g_sense == gen) __nanosleep(32);
        }
        __threadfence();
    }
    __syncthreads();
}

// ---------------------------------------------------------------------------
// Squash phase: blocks 0..127 active; block -> (b = bx>>2, oq4 = bx&3).
// 1024 threads = 32 float4-cols x 32 k-slices; smem tree; lane groups of 4
// = one 16-atom capsule. Fixed order -> deterministic.
// ---------------------------------------------------------------------------
__device__ __forceinline__ void squash_phase(char* smem, int nb, float scale,
                                             const float* __restrict__ bias,
                                             float* __restrict__ dst, int accumulate) {
    if (blockIdx.x < 128) {
        float4* red = (float4*)smem;                 // [32][33] float4 (17 KB)
        const int b    = blockIdx.x >> 2;
        const int oq4  = blockIdx.x & 3;
        const int col  = threadIdx.x & 31;
        const int ks   = threadIdx.x >> 5;
        const int gcol = b * 128 + oq4 * 32 + col;   // global float4 column
        const float4* gp = (const float4*)g_part;

        float4 s = make_float4(0.f, 0.f, 0.f, 0.f);
        for (int k = ks; k < nb; k += 32) {
            float4 v = gp[(size_t)k * (BO / 4) + gcol];
            s.x += v.x; s.y += v.y; s.z += v.z; s.w += v.w;
        }
        red[ks * 33 + col] = s;
        __syncthreads();

        if (threadIdx.x < 32) {
            float4 sum = red[col];
#pragma unroll
            for (int j = 1; j < 32; j++) {
                float4 v = red[j * 33 + col];
                sum.x += v.x; sum.y += v.y; sum.z += v.z; sum.w += v.w;
            }
            const float4 bi = ((const float4*)bias)[oq4 * 32 + col];
            float4 val;
            val.x = fmaf(sum.x, scale, bi.x);
            val.y = fmaf(sum.y, scale, bi.y);
            val.z = fmaf(sum.z, scale, bi.z);
            val.w = fmaf(sum.w, scale, bi.w);

            float n2 = (val.x * val.x + val.y * val.y) + (val.z * val.z + val.w * val.w);
            n2 += __shfl_xor_sync(0xffffffffu, n2, 1);
            n2 += __shfl_xor_sync(0xffffffffu, n2, 2);
            const float f = sqrtf(n2) / (1.f + n2);

            float4* dp = (float4*)dst + gcol;
            if (accumulate) {
                float4 cur = *dp;
                cur.x = fmaf(val.x, f, cur.x); cur.y = fmaf(val.y, f, cur.y);
                cur.z = fmaf(val.z, f, cur.z); cur.w = fmaf(val.w, f, cur.w);
                *dp = cur;
            } else {
                *dp = make_float4(val.x * f, val.y * f, val.z * f, val.w * f);
            }
        }
    }
    __syncthreads();
}

// ---------------------------------------------------------------------------
// HMMA pass over this block's contiguous i-range [ilo, ihi).
// Per i: votes tile [32b x 512o] = x[32b,16c] * W[i][16c,512o] (fp16/fp32 mma).
// ROUTE=0: accumulate Sum_i votes in fragment registers (iter0 partial).
// ROUTE=1: stage tile in smem; warp wid = b, lane = d does dot(act)/softmax/
//          weighted accumulate (the routing pass, votes never touch global).
// W/x staged fp32->fp16 double-buffered; W read with __ldg (L2-resident after
// pass 0, so passes 1-2 generate no DRAM traffic for W).
// ---------------------------------------------------------------------------
template <int ROUTE>
__device__ __forceinline__ void hmma_pass(const float* __restrict__ x,
                                          const float* __restrict__ w, int nb) {
    extern __shared__ __align__(16) char smem[];
    const int t    = threadIdx.x;
    const int lane = t & 31;
    const int wid  = t >> 5;
    const int mh   = wid & 1;
    const int ng   = wid >> 1;          // 0..15
    const int bx   = blockIdx.x;
    const int ilo  = (bx * II) / nb;
    const int ihi  = ((bx + 1) * II) / nb;

    const unsigned sb = (unsigned)__cvta_generic_to_shared(smem);

    // staging roles
    const int wk = t >> 6;              // W row (c) 0..15
    const int wj = t & 63;              // W chunk 0..63
    const unsigned wst = sb + wk * 1024 + ((wj ^ (wk & 7)) << 4);
    const int xb = t >> 2, xq = t & 3;  // x role (t < 128)
    const unsigned xst = sb + XBUF_OFF + xb * 48 + xq * 8;

    // ldmatrix source addresses
    const int al = lane & 15, ak = lane >> 4;
    const unsigned aaddr = sb + XBUF_OFF + (mh * 16 + al) * 48 + ak * 16;
    const int bk = lane & 15, bjo = lane >> 4;
    unsigned baddr[2];
#pragma unroll
    for (int g2 = 0; g2 < 2; g2++) {
        int j = ng * 4 + g2 * 2 + bjo;
        baddr[g2] = sb + bk * 1024 + ((j ^ (bk & 7)) << 4);
    }

    const int g  = lane >> 2;           // fragment row group
    const int tq = lane & 3;            // fragment col quad
    const int brow0 = mh * 16 + g;

    // fragment staging addresses (ROUTE only)
    const unsigned vs0 = sb + VSTAGE_OFF + brow0 * VROW_B + ng * 64 + tq * 4;
    const unsigned vs1 = vs0 + 8 * VROW_B;
    // route read address: warp wid = b reads its row, lane d at o = d*16
    const unsigned raddr = sb + VSTAGE_OFF + wid * VROW_B + lane * 32;

    float sacc[16];
    ull   racc[8];
    ull   arp[8];
    if (ROUTE) {
        const float4* ap = (const float4*)(g_actS + (wid * DD + lane) * AA);
        float4 a0 = ap[0], a1 = ap[1], a2 = ap[2], a3 = ap[3];
        arp[0] = pack2(a0.x, a0.y); arp[1] = pack2(a0.z, a0.w);
        arp[2] = pack2(a1.x, a1.y); arp[3] = pack2(a1.z, a1.w);
        arp[4] = pack2(a2.x, a2.y); arp[5] = pack2(a2.z, a2.w);
        arp[6] = pack2(a3.x, a3.y); arp[7] = pack2(a3.z, a3.w);
#pragma unroll
        for (int k = 0; k < 8; k++) racc[k] = 0ull;
    } else {
#pragma unroll
        for (int k = 0; k < 16; k++) sacc[k] = 0.f;
    }

    // prologue: load W(ilo), x(ilo) fp32 into registers (L2-cached via __ldg)
    float4 wr0, wr1, xr;
    {
        const float4* ws = (const float4*)(w + (size_t)ilo * CC * OO + wk * OO + wj * 8);
        wr0 = __ldg(ws); wr1 = __ldg(ws + 1);
        if (t < 128)
            xr = __ldg((const float4*)(x + ((size_t)xb * II + ilo) * CC) + xq);
    }

    for (int i = ilo; i < ihi; i++) {
        const int buf = (i - ilo) & 1;
        const unsigned wb = buf * WBUF_BYTES;
        const unsigned xbo = buf * XBUF_BYTES;

        // stage fp16 W/x tiles
        {
            unsigned h0 = cvt_h2(wr0.y, wr0.x), h1 = cvt_h2(wr0.w, wr0.z);
            unsigned h2 = cvt_h2(wr1.y, wr1.x), h3 = cvt_h2(wr1.w, wr1.z);
            asm volatile("st.shared.v4.b32 [%0], {%1,%2,%3,%4};"
                         :: "r"(wst + wb), "r"(h0), "r"(h1), "r"(h2), "r"(h3));
            if (t < 128) {
                unsigned x0 = cvt_h2(xr.y, xr.x), x1 = cvt_h2(xr.w, xr.z);
                asm volatile("st.shared.v2.b32 [%0], {%1,%2};"
                             :: "r"(xst + xbo), "r"(x0), "r"(x1));
            }
        }
        __syncthreads();   // tiles ready; also orders prior vstage reads before refill

        // prefetch i+1 (overlaps with compute below)
        if (i + 1 < ihi) {
            const float4* ws = (const float4*)(w + (size_t)(i + 1) * CC * OO + wk * OO + wj * 8);
            wr0 = __ldg(ws); wr1 = __ldg(ws + 1);
            if (t < 128)
                xr = __ldg((const float4*)(x + ((size_t)xb * II + i + 1) * CC) + xq);
        }

        // A fragment (x): one ldmatrix.x4
        unsigned a0, a1, a2, a3;
        ldsm_x4(a0, a1, a2, a3, aaddr + xbo);

#pragma unroll
        for (int g2 = 0; g2 < 2; g2++) {
            unsigned b0, b1, b2, b3;
            ldsm_x4_trans(b0, b1, b2, b3, baddr[g2] + wb);
#pragma unroll
            for (int nt = 0; nt < 2; nt++) {
                float d0, d1, d2, d3;
                mma16816(d0, d1, d2, d3, a0, a1, a2, a3,
                         nt ? b2 : b0, nt ? b3 : b1);
                const int ntile = g2 * 2 + nt;
                if (ROUTE) {
                    const unsigned off = ntile * 16;
                    asm volatile("st.shared.b32 [%0], %1;" :: "r"(vs0 + off), "r"(cvt_h2(d1, d0)));
                    asm volatile("st.shared.b32 [%0], %1;" :: "r"(vs1 + off), "r"(cvt_h2(d3, d2)));
                } else {
                    const int s = ntile * 4;
                    sacc[s] += d0; sacc[s + 1] += d1; sacc[s + 2] += d2; sacc[s + 3] += d3;
                }
            }
        }

        if (ROUTE) {
            __syncthreads();   // all fragments staged

            // route math: warp = b (wid), lane = d; votes row from smem
            uint4 c0, c1;
            asm volatile("ld.shared.v4.b32 {%0,%1,%2,%3}, [%4];"
                         : "=r"(c0.x), "=r"(c0.y), "=r"(c0.z), "=r"(c0.w) : "r"(raddr));
            asm volatile("ld.shared.v4.b32 {%0,%1,%2,%3}, [%4];"
                         : "=r"(c1.x), "=r"(c1.y), "=r"(c1.z), "=r"(c1.w) : "r"(raddr + 16));

            ull vpk[8];
            {
                const __half2* h0 = (const __half2*)&c0;
                const __half2* h1 = (const __half2*)&c1;
#pragma unroll
                for (int j = 0; j < 4; j++) {
                    float2 f = __half22float2(h0[j]); vpk[j]     = pack2(f.x, f.y);
                    float2 q = __half22float2(h1[j]); vpk[4 + j] = pack2(q.x, q.y);
                }
            }

            ull u2 = 0ull;
#pragma unroll
            for (int k = 0; k < 8; k++) fma2(u2, vpk[k], arp[k]);
            float ulo, uhi; unpack2(u2, ulo, uhi);
            const float u = ulo + uhi;

            // softmax over d (32 lanes); |u| small enough to skip max-subtract
            float e = __expf(u);
            float s = e;
#pragma unroll
            for (int o = 16; o >= 1; o >>= 1) s += __shfl_xor_sync(0xffffffffu, s, o);
            const float r = __fdividef(e, s);
            const ull rr = pack2(r, r);
#pragma unroll
            for (int k = 0; k < 8; k++) fma2(racc[k], rr, vpk[k]);
        }
    }

    // deterministic per-block partial write (row = blockIdx.x)
    if (ROUTE) {
        float* dst = g_part + (size_t)bx * BO + (wid * DD + lane) * AA;
#pragma unroll
        for (int k = 0; k < 4; k++) {
            float l0, h0, l1, h1;
            unpack2(racc[2 * k], l0, h0);
            unpack2(racc[2 * k + 1], l1, h1);
            ((float4*)dst)[k] = make_float4(l0, h0, l1, h1);
        }
    } else {
        float* pr = g_part + (size_t)bx * BO;
#pragma unroll
        for (int ntile = 0; ntile < 4; ntile++) {
            const int o = (ng * 4 + ntile) * 8 + tq * 2;
            const int s = ntile * 4;
            *(float2*)(pr + brow0 * OO + o)       = make_float2(sacc[s],     sacc[s + 1]);
            *(float2*)(pr + (brow0 + 8) * OO + o) = make_float2(sacc[s + 2], sacc[s + 3]);
        }
    }
}

// ---------------------------------------------------------------------------
// Fused persistent kernel: mma-sum -> squash0 -> mma-route -> squash1 ->
// mma-route -> squash2. Votes are never materialized in global memory.
// ---------------------------------------------------------------------------
__global__ __launch_bounds__(NT, 1) void caps_kernel(const float* __restrict__ x,
                                                     const float* __restrict__ w,
                                                     const float* __restrict__ bias,
                                                     float* __restrict__ out,
                                                     int nb) {
    extern __shared__ __align__(16) char smem[];

    hmma_pass<0>(x, w, nb);                                 // iter0 vote-sum partials
    grid_sync(nb);
    squash_phase(smem, nb, 1.0f / 32.0f, bias, g_actS, 0);  // actS = act0
    grid_sync(nb);
    hmma_pass<1>(x, w, nb);                                 // route pass 1 (W from L2)
    grid_sync(nb);
    squash_phase(smem, nb, 1.0f, bias, g_actS, 1);          // actS = act0 + act1
    grid_sync(nb);
    hmma_pass<1>(x, w, nb);                                 // route pass 2 (W from L2)
    grid_sync(nb);
    squash_phase(smem, nb, 1.0f, bias, out, 0);             // final activation
}

// ---------------------------------------------------------------------------
extern "C" void kernel_launch(void* const* d_in, const int* in_sizes, int n_in,
                              void* d_out, int out_size) {
    const float* x    = (const float*)d_in[0];
    const float* w    = (const float*)d_in[1];
    const float* bias = (const float*)d_in[2];
    float* out = (float*)d_out;

    int dev = 0, sm = 148;
    cudaGetDevice(&dev);
    cudaDeviceGetAttribute(&sm, cudaDevAttrMultiProcessorCount, dev);
    int nb = sm < NBMAX ? sm : NBMAX;
    if (nb < 128) nb = 128;  // squash uses 128 blocks; all real targets have >=128 SMs

    cudaFuncSetAttribute(caps_kernel, cudaFuncAttributeMaxDynamicSharedMemorySize, SMEM_TOTAL);
    caps_kernel<<<nb, NT, SMEM_TOTAL>>>(x, w, bias, out, nb);
}

// round 14
// speedup vs baseline: 1.2981x; 1.2981x over previous
#include <cuda_runtime.h>
#include <cuda_fp16.h>
#include <cstdint>

// Problem constants (fixed by the dataset)
#define BB 32      // batch
#define II 2048    // input capsules
#define CC 16      // input atoms (contraction dim)
#define DD 32      // output capsules
#define AA 16      // output atoms
#define OO 512     // DD*AA
#define BO (BB*OO) // 16384
#define NBMAX 160
#define NT 1024

typedef unsigned long long ull;

// Scratch (static __device__ arrays: no dynamic allocation)
__device__ __half g_votes[(size_t)II * BB * OO];     // [i][b][o] fp16, 67 MB
__device__ float  g_part[(size_t)NBMAX * BO];        // per-block partials, 10.5 MB
__device__ float  g_actS[BO];                        // act0, then act0+act1
__device__ unsigned g_count;                          // barrier arrive counter (self-resetting)
__device__ volatile unsigned g_sense;                 // barrier generation (monotonic)

// ---------------- packed f32x2 helpers (route phase) ----------------
__device__ __forceinline__ ull pack2(float lo, float hi) {
    ull r; asm("mov.b64 %0, {%1,%2};" : "=l"(r) : "f"(lo), "f"(hi)); return r;
}
__device__ __forceinline__ void unpack2(ull v, float& lo, float& hi) {
    asm("mov.b64 {%0,%1}, %2;" : "=f"(lo), "=f"(hi) : "l"(v));
}
__device__ __forceinline__ void fma2(ull& d, ull a, ull b) {
    asm("fma.rn.f32x2 %0, %1, %2, %0;" : "+l"(d) : "l"(a), "l"(b));
}

// ---------------- mma helpers ----------------
__device__ __forceinline__ void ldsm_x4(unsigned& r0, unsigned& r1, unsigned& r2, unsigned& r3,
                                        unsigned addr) {
    asm volatile("ldmatrix.sync.aligned.m8n8.x4.shared.b16 {%0,%1,%2,%3}, [%4];"
                 : "=r"(r0), "=r"(r1), "=r"(r2), "=r"(r3) : "r"(addr));
}
__device__ __forceinline__ void ldsm_x4_trans(unsigned& r0, unsigned& r1, unsigned& r2, unsigned& r3,
                                              unsigned addr) {
    asm volatile("ldmatrix.sync.aligned.m8n8.x4.trans.shared.b16 {%0,%1,%2,%3}, [%4];"
                 : "=r"(r0), "=r"(r1), "=r"(r2), "=r"(r3) : "r"(addr));
}
__device__ __forceinline__ void mma16816(float& d0, float& d1, float& d2, float& d3,
                                         unsigned a0, unsigned a1, unsigned a2, unsigned a3,
                                         unsigned b0, unsigned b1) {
    asm volatile(
        "mma.sync.aligned.m16n8k16.row.col.f32.f16.f16.f32 "
        "{%0,%1,%2,%3}, {%4,%5,%6,%7}, {%8,%9}, {%10,%11,%12,%13};"
        : "=f"(d0), "=f"(d1), "=f"(d2), "=f"(d3)
        : "r"(a0), "r"(a1), "r"(a2), "r"(a3), "r"(b0), "r"(b1),
          "f"(0.f), "f"(0.f), "f"(0.f), "f"(0.f));
}
__device__ __forceinline__ unsigned cvt_h2(float hi, float lo) {
    unsigned v; asm("cvt.rn.f16x2.f32 %0, %1, %2;" : "=r"(v) : "f"(hi), "f"(lo)); return v;
}

// smem layout: W fp16 [2][16384] @0; x fp16 [2][1536] @32768; vote stage @35840
#define WBUF_BYTES 16384
#define XBUF_OFF   32768
#define XBUF_BYTES 1536              // 32 rows x 48 B (32 B data + 16 B pad)
#define VSTAGE_OFF 35840
#define VROW_B     1040              // 1024 B data + 16 B pad (bank shift of 4)
#define SMEM_TOTAL (VSTAGE_OFF + BB * VROW_B + 64)

// ---------------------------------------------------------------------------
// Software grid barrier (sense-reversing). nb blocks co-resident (1/SM).
// ---------------------------------------------------------------------------
__device__ __forceinline__ void grid_sync(int nb) {
    __syncthreads();
    if (threadIdx.x == 0) {
        unsigned gen = g_sense;
        __threadfence();
        if (atomicAdd(&g_count, 1u) == (unsigned)(nb - 1)) {
            g_count = 0;
            __threadfence();
            g_sense = gen + 1;
        } else {
            while (g_sense == gen) __nanosleep(32);
        }
        __threadfence();
    }
    __syncthreads();
}

// ---------------------------------------------------------------------------
// Squash phase: blocks 0..127 active; block -> (b = bx>>2, oq4 = bx&3).
// 1024 threads = 32 float4-cols x 32 k-slices; smem tree; lane groups of 4
// = one 16-atom capsule. Fixed order -> deterministic.
// ---------------------------------------------------------------------------
__device__ __forceinline__ void squash_phase(char* smem, int nb, float scale,
                                             const float* __restrict__ bias,
                                             float* __restrict__ dst, int accumulate) {
    if (blockIdx.x < 128) {
        float4* red = (float4*)smem;                 // [32][33] float4 (17 KB)
        const int b    = blockIdx.x >> 2;
        const int oq4  = blockIdx.x & 3;
        const int col  = threadIdx.x & 31;
        const int ks   = threadIdx.x >> 5;
        const int gcol = b * 128 + oq4 * 32 + col;   // global float4 column
        const float4* gp = (const float4*)g_part;

        float4 s = make_float4(0.f, 0.f, 0.f, 0.f);
        for (int k = ks; k < nb; k += 32) {
            float4 v = gp[(size_t)k * (BO / 4) + gcol];
            s.x += v.x; s.y += v.y; s.z += v.z; s.w += v.w;
        }
        red[ks * 33 + col] = s;
        __syncthreads();

        if (threadIdx.x < 32) {
            float4 sum = red[col];
#pragma unroll
            for (int j = 1; j < 32; j++) {
                float4 v = red[j * 33 + col];
                sum.x += v.x; sum.y += v.y; sum.z += v.z; sum.w += v.w;
            }
            const float4 bi = ((const float4*)bias)[oq4 * 32 + col];
            float4 val;
            val.x = fmaf(sum.x, scale, bi.x);
            val.y = fmaf(sum.y, scale, bi.y);
            val.z = fmaf(sum.z, scale, bi.z);
            val.w = fmaf(sum.w, scale, bi.w);

            float n2 = (val.x * val.x + val.y * val.y) + (val.z * val.z + val.w * val.w);
            n2 += __shfl_xor_sync(0xffffffffu, n2, 1);
            n2 += __shfl_xor_sync(0xffffffffu, n2, 2);
            const float f = sqrtf(n2) / (1.f + n2);

            float4* dp = (float4*)dst + gcol;
            if (accumulate) {
                float4 cur = *dp;
                cur.x = fmaf(val.x, f, cur.x); cur.y = fmaf(val.y, f, cur.y);
                cur.z = fmaf(val.z, f, cur.z); cur.w = fmaf(val.w, f, cur.w);
                *dp = cur;
            } else {
                *dp = make_float4(val.x * f, val.y * f, val.z * f, val.w * f);
            }
        }
    }
    __syncthreads();
}

// ---------------------------------------------------------------------------
// Route phase: block bx owns i in [ilo, ihi); warp = one b; lane = one d.
// Prefetch DISTANCE 2: loads for i+1 and i+2 both in flight while the chain
// of i runs (16 KB/SM outstanding -> latency fully covered).
// STREAM=1 (pass 2): __ldcs streaming (votes dead after).
// ---------------------------------------------------------------------------
template <int STREAM>
__device__ __forceinline__ void route_phase(int nb) {
    const int b    = threadIdx.x >> 5;
    const int lane = threadIdx.x & 31;
    const int bx   = blockIdx.x;
    const int ilo  = (bx * II) / nb;
    const int ihi  = ((bx + 1) * II) / nb;
    const int d    = lane;

    ull arp[8];
    {
        const float4* ap = (const float4*)(g_actS + (b * DD + d) * AA);
        float4 a0 = ap[0], a1 = ap[1], a2 = ap[2], a3 = ap[3];
        arp[0] = pack2(a0.x, a0.y); arp[1] = pack2(a0.z, a0.w);
        arp[2] = pack2(a1.x, a1.y); arp[3] = pack2(a1.z, a1.w);
        arp[4] = pack2(a2.x, a2.y); arp[5] = pack2(a2.z, a2.w);
        arp[6] = pack2(a3.x, a3.y); arp[7] = pack2(a3.z, a3.w);
    }

    ull acc[8];
#pragma unroll
    for (int k = 0; k < 8; k++) acc[k] = 0ull;

    const uint4* vbase = (const uint4*)(g_votes + (size_t)b * OO + d * 16);
    const int stride = (BB * OO) / 8;                 // uint4 stride per i

    uint4 p0, p1, q0, q1;
    {
        const uint4* a = vbase + (size_t)ilo * stride;
        p0 = STREAM ? __ldcs(a) : __ldg(a);
        p1 = STREAM ? __ldcs(a + 1) : __ldg(a + 1);
    }
    if (ilo + 1 < ihi) {
        const uint4* a = vbase + (size_t)(ilo + 1) * stride;
        q0 = STREAM ? __ldcs(a) : __ldg(a);
        q1 = STREAM ? __ldcs(a + 1) : __ldg(a + 1);
    }

    for (int i = ilo; i < ihi; i++) {
        uint4 c0 = p0, c1 = p1;
        p0 = q0; p1 = q1;
        if (i + 2 < ihi) {                    // issue distance-2 prefetch
            const uint4* np = vbase + (size_t)(i + 2) * stride;
            q0 = STREAM ? __ldcs(np)     : __ldg(np);
            q1 = STREAM ? __ldcs(np + 1) : __ldg(np + 1);
        }

        ull vpk[8];
        {
            const __half2* h0 = (const __half2*)&c0;
            const __half2* h1 = (const __half2*)&c1;
#pragma unroll
            for (int j = 0; j < 4; j++) {
                float2 f = __half22float2(h0[j]); vpk[j]     = pack2(f.x, f.y);
                float2 g = __half22float2(h1[j]); vpk[4 + j] = pack2(g.x, g.y);
            }
        }

        ull u2 = 0ull;
#pragma unroll
        for (int k = 0; k < 8; k++) fma2(u2, vpk[k], arp[k]);
        float ulo, uhi; unpack2(u2, ulo, uhi);
        const float u = ulo + uhi;

        // softmax over d (32 lanes); |u| small enough to skip max-subtract
        float e = __expf(u);
        float s = e;
#pragma unroll
        for (int o = 16; o >= 1; o >>= 1) s += __shfl_xor_sync(0xffffffffu, s, o);
        const float r = __fdividef(e, s);
        const ull rr = pack2(r, r);
#pragma unroll
        for (int k = 0; k < 8; k++) fma2(acc[k], rr, vpk[k]);
    }

    float* dst = g_part + (size_t)bx * BO + (b * DD + d) * AA;
#pragma unroll
    for (int k = 0; k < 4; k++) {
        float l0, h0, l1, h1;
        unpack2(acc[2 * k], l0, h0);
        unpack2(acc[2 * k + 1], l1, h1);
        ((float4*)dst)[k] = make_float4(l0, h0, l1, h1);
    }
}

// ---------------------------------------------------------------------------
// Fused persistent kernel.
// ---------------------------------------------------------------------------
__global__ __launch_bounds__(NT, 1) void caps_kernel(const float* __restrict__ x,
                                                     const float* __restrict__ w,
                                                     const float* __restrict__ bias,
                                                     float* __restrict__ out,
                                                     int nb) {
    extern __shared__ __align__(16) char smem[];

    // ================= Phase 1: votes (HMMA, distance-2 W prefetch) ========
    // Per i: D[32b,512o] = A[32b,16c] x B[16c,512o] via mma.sync.m16n8k16.
    // TWO register prefetch sets (A/B): the load issued at iteration `it`
    // is consumed at `it+2`, so two iterations cover DRAM latency and W
    // bytes-in-flight doubles (16 KB/SM). Fragments staged in padded smem,
    // then written out as contiguous STG.128.
    {
        const int t    = threadIdx.x;
        const int lane = t & 31;
        const int wid  = t >> 5;
        const int mh   = wid & 1;
        const int ng   = wid >> 1;          // 0..15
        const int bx   = blockIdx.x;
        const int n    = (II - bx + nb - 1) / nb;

        const unsigned sb = (unsigned)__cvta_generic_to_shared(smem);

        // staging roles
        const int wk = t >> 6;              // W row (c) 0..15
        const int wj = t & 63;              // W chunk 0..63
        const unsigned wst = sb + wk * 1024 + ((wj ^ (wk & 7)) << 4);
        const int xb = t >> 2, xq = t & 3;  // x role (t < 128)
        const unsigned xst = sb + XBUF_OFF + xb * 48 + xq * 8;

        // ldmatrix source addresses
        const int al = lane & 15, ak = lane >> 4;
        const unsigned aaddr = sb + XBUF_OFF + (mh * 16 + al) * 48 + ak * 16;
        const int bk = lane & 15, bjo = lane >> 4;
        unsigned baddr[2];
#pragma unroll
        for (int g2 = 0; g2 < 2; g2++) {
            int j = ng * 4 + g2 * 2 + bjo;
            baddr[g2] = sb + bk * 1024 + ((j ^ (bk & 7)) << 4);
        }

        const int g  = lane >> 2;           // fragment row group
        const int tq = lane & 3;            // fragment col quad
        const int brow0 = mh * 16 + g;

        // vote staging addresses (row*1040: bank shift 4/row -> conflict-free)
        const unsigned vs0 = sb + VSTAGE_OFF + brow0 * VROW_B + ng * 64 + tq * 4;
        const unsigned vs1 = vs0 + 8 * VROW_B;
        const unsigned wo_s0 = sb + VSTAGE_OFF + (t >> 6) * VROW_B + (t & 63) * 16;
        const unsigned wo_s1 = sb + VSTAGE_OFF + ((t + 1024) >> 6) * VROW_B + (t & 63) * 16;

        float sacc[16];
#pragma unroll
        for (int k = 0; k < 16; k++) sacc[k] = 0.f;

        // prologue: prefetch sets A (it=0) and B (it=1)
        float4 wA0, wA1, xA, wB0, wB1, xB;
        {
            const float4* ws = (const float4*)(w + (size_t)bx * CC * OO + wk * OO + wj * 8);
            wA0 = __ldcs(ws); wA1 = __ldcs(ws + 1);
            if (t < 128)
                xA = __ldcs((const float4*)(x + ((size_t)xb * II + bx) * CC) + xq);
        }
        if (n > 1) {
            const int i1 = bx + nb;
            const float4* ws = (const float4*)(w + (size_t)i1 * CC * OO + wk * OO + wj * 8);
            wB0 = __ldcs(ws); wB1 = __ldcs(ws + 1);
            if (t < 128)
                xB = __ldcs((const float4*)(x + ((size_t)xb * II + i1) * CC) + xq);
        }

        for (int it = 0; it < n; it++) {
            const int i = bx + it * nb;
            const int buf = it & 1;
            const unsigned wb = buf * WBUF_BYTES;
            const unsigned xbo = buf * XBUF_BYTES;

            // stage current prefetch set (A for even it, B for odd)
            {
                const float4 w0 = buf ? wB0 : wA0;
                const float4 w1 = buf ? wB1 : wA1;
                unsigned h0 = cvt_h2(w0.y, w0.x), h1 = cvt_h2(w0.w, w0.z);
                unsigned h2 = cvt_h2(w1.y, w1.x), h3 = cvt_h2(w1.w, w1.z);
                asm volatile("st.shared.v4.b32 [%0], {%1,%2,%3,%4};"
                             :: "r"(wst + wb), "r"(h0), "r"(h1), "r"(h2), "r"(h3));
                if (t < 128) {
                    const float4 xx = buf ? xB : xA;
                    unsigned x0 = cvt_h2(xx.y, xx.x), x1 = cvt_h2(xx.w, xx.z);
                    asm volatile("st.shared.v2.b32 [%0], {%1,%2};"
                                 :: "r"(xst + xbo), "r"(x0), "r"(x1));
                }
            }
            __syncthreads();   // tiles ready; also orders prev writeout before vstage reuse

            // issue distance-2 prefetch into the just-consumed set
            if (it + 2 < n) {
                const int i2 = bx + (it + 2) * nb;
                const float4* ws = (const float4*)(w + (size_t)i2 * CC * OO + wk * OO + wj * 8);
                if (buf) { wB0 = __ldcs(ws); wB1 = __ldcs(ws + 1); }
                else     { wA0 = __ldcs(ws); wA1 = __ldcs(ws + 1); }
                if (t < 128) {
                    const float4 xv = __ldcs((const float4*)(x + ((size_t)xb * II + i2) * CC) + xq);
                    if (buf) xB = xv; else xA = xv;
                }
            }

            // A fragment (x): one ldmatrix.x4
            unsigned a0, a1, a2, a3;
            ldsm_x4(a0, a1, a2, a3, aaddr + xbo);

#pragma unroll
            for (int g2 = 0; g2 < 2; g2++) {
                unsigned b0, b1, b2, b3;
                ldsm_x4_trans(b0, b1, b2, b3, baddr[g2] + wb);
#pragma unroll
                for (int nt = 0; nt < 2; nt++) {
                    float d0, d1, d2, d3;
                    mma16816(d0, d1, d2, d3, a0, a1, a2, a3,
                             nt ? b2 : b0, nt ? b3 : b1);
                    const int ntile = g2 * 2 + nt;
                    const unsigned off = ntile * 16;
                    asm volatile("st.shared.b32 [%0], %1;" :: "r"(vs0 + off), "r"(cvt_h2(d1, d0)));
                    asm volatile("st.shared.b32 [%0], %1;" :: "r"(vs1 + off), "r"(cvt_h2(d3, d2)));
                    const int s = ntile * 4;
                    sacc[s] += d0; sacc[s + 1] += d1; sacc[s + 2] += d2; sacc[s + 3] += d3;
                }
            }
            __syncthreads();   // all frags staged

            // coalesced writeout: 32 KB contiguous per (block, i)
            {
                uint4 v0, v1;
                asm volatile("ld.shared.v4.b32 {%0,%1,%2,%3}, [%4];"
                             : "=r"(v0.x), "=r"(v0.y), "=r"(v0.z), "=r"(v0.w) : "r"(wo_s0));
                asm volatile("ld.shared.v4.b32 {%0,%1,%2,%3}, [%4];"
                             : "=r"(v1.x), "=r"(v1.y), "=r"(v1.z), "=r"(v1.w) : "r"(wo_s1));
                uint4* gdst = (uint4*)(g_votes + (size_t)i * BO);
                gdst[t]        = v0;
                gdst[t + 1024] = v1;
            }
        }

        // deterministic per-block partial write (row = blockIdx.x)
        float* pr = g_part + (size_t)bx * BO;
#pragma unroll
        for (int ntile = 0; ntile < 4; ntile++) {
            const int o = (ng * 4 + ntile) * 8 + tq * 2;
            const int s = ntile * 4;
            *(float2*)(pr + brow0 * OO + o)       = make_float2(sacc[s],     sacc[s + 1]);
            *(float2*)(pr + (brow0 + 8) * OO + o) = make_float2(sacc[s + 2], sacc[s + 3]);
        }
    }

    grid_sync(nb);
    squash_phase(smem, nb, 1.0f / 32.0f, bias, g_actS, 0);  // actS = act0
    grid_sync(nb);
    route_phase<0>(nb);                                     // softmax(u(act0)); keep votes in L2
    grid_sync(nb);
    squash_phase(smem, nb, 1.0f, bias, g_actS, 1);          // actS = act0 + act1
    grid_sync(nb);
    route_phase<1>(nb);                                     // softmax(u(act0+act1)); streaming reads
    grid_sync(nb);
    squash_phase(smem, nb, 1.0f, bias, out, 0);             // final activation
}

// ---------------------------------------------------------------------------
extern "C" void kernel_launch(void* const* d_in, const int* in_sizes, int n_in,
                              void* d_out, int out_size) {
    const float* x    = (const float*)d_in[0];
    const float* w    = (const float*)d_in[1];
    const float* bias = (const float*)d_in[2];
    float* out = (float*)d_out;

    int dev = 0, sm = 148;
    cudaGetDevice(&dev);
    cudaDeviceGetAttribute(&sm, cudaDevAttrMultiProcessorCount, dev);
    int nb = sm < NBMAX ? sm : NBMAX;
    if (nb < 128) nb = 128;  // squash uses 128 blocks; all real targets have >=128 SMs

    cudaFuncSetAttribute(caps_kernel, cudaFuncAttributeMaxDynamicSharedMemorySize, SMEM_TOTAL);
    caps_kernel<<<nb, NT, SMEM_TOTAL>>>(x, w, bias, out, nb);
}